// round 8
// baseline (speedup 1.0000x reference)
#include <cuda_runtime.h>
#include <cuda_bf16.h>
#include <cuda_fp16.h>
#include <math.h>
#include <math_constants.h>
#include <cstdint>

// Problem constants
#define BB 2
#define SS 2048
#define DD 1024
#define HH 16
#define DHH 64

// log2(e)/8  (folded into Q so softmax is pure 2^x)
#define QSCALE 0.18033688011112042f
#define WSC 256.0f
#define WSCI (1.0f / 256.0f)

// ---------------- device scratch (no cudaMalloc allowed) ----------------
__device__ __align__(16) __half g_xf[4096 * 1024];          // x, fp16
__device__ __align__(16) __half g_wh[3072 * 1024];          // wqkv*256 hi
__device__ __align__(16) __half g_wl[3072 * 1024];          // wqkv*256 lo
__device__ __align__(16) __half g_woh[1024 * 1024];         // wo*256 hi
__device__ __align__(16) __half g_wol[1024 * 1024];         // wo*256 lo
__device__ __align__(16) __half g_af[4096 * 1024];          // attn out, fp16

// Q,K (bf16 hi/lo) and V (fp16 hi/lo) in [b][h][s][d] layout
__device__ __align__(16) __nv_bfloat16 g_qh[BB * HH * SS * DHH];
__device__ __align__(16) __nv_bfloat16 g_ql[BB * HH * SS * DHH];
__device__ __align__(16) __nv_bfloat16 g_kh[BB * HH * SS * DHH];
__device__ __align__(16) __nv_bfloat16 g_kl[BB * HH * SS * DHH];
__device__ __align__(16) __half       g_vh[BB * HH * SS * DHH];
__device__ __align__(16) __half       g_vl[BB * HH * SS * DHH];

// ============================ helpers ============================
__device__ __forceinline__ uint32_t smem_u32(const void* p) {
    uint32_t a;
    asm("{ .reg .u64 t; cvta.to.shared.u64 t, %1; cvt.u32.u64 %0, t; }" : "=r"(a) : "l"(p));
    return a;
}

__device__ __forceinline__ void ldm_x4(uint32_t* r, uint32_t addr) {
    asm volatile("ldmatrix.sync.aligned.m8n8.x4.shared.b16 {%0,%1,%2,%3}, [%4];"
                 : "=r"(r[0]), "=r"(r[1]), "=r"(r[2]), "=r"(r[3]) : "r"(addr));
}
__device__ __forceinline__ void ldm_x4_t(uint32_t* r, uint32_t addr) {
    asm volatile("ldmatrix.sync.aligned.m8n8.x4.trans.shared.b16 {%0,%1,%2,%3}, [%4];"
                 : "=r"(r[0]), "=r"(r[1]), "=r"(r[2]), "=r"(r[3]) : "r"(addr));
}

__device__ __forceinline__ void mma_bf16(float* d, const uint32_t* a, const uint32_t* b) {
    asm volatile(
        "mma.sync.aligned.m16n8k16.row.col.f32.bf16.bf16.f32 "
        "{%0,%1,%2,%3}, {%4,%5,%6,%7}, {%8,%9}, {%0,%1,%2,%3};"
        : "+f"(d[0]), "+f"(d[1]), "+f"(d[2]), "+f"(d[3])
        : "r"(a[0]), "r"(a[1]), "r"(a[2]), "r"(a[3]), "r"(b[0]), "r"(b[1]));
}
__device__ __forceinline__ void mma_f16(float* d, const uint32_t* a, const uint32_t* b) {
    asm volatile(
        "mma.sync.aligned.m16n8k16.row.col.f32.f16.f16.f32 "
        "{%0,%1,%2,%3}, {%4,%5,%6,%7}, {%8,%9}, {%0,%1,%2,%3};"
        : "+f"(d[0]), "+f"(d[1]), "+f"(d[2]), "+f"(d[3])
        : "r"(a[0]), "r"(a[1]), "r"(a[2]), "r"(a[3]), "r"(b[0]), "r"(b[1]));
}

__device__ __forceinline__ void cp16(uint32_t dst, const void* src) {
    asm volatile("cp.async.cg.shared.global [%0], [%1], 16;" :: "r"(dst), "l"(src));
}
#define CP_COMMIT() asm volatile("cp.async.commit_group;" ::: "memory")
#define CP_WAIT(n)  asm volatile("cp.async.wait_group %0;" :: "n"(n) : "memory")

__device__ __forceinline__ float ex2f(float x) {
    float y;
    asm("ex2.approx.ftz.f32 %0, %1;" : "=f"(y) : "f"(x));
    return y;
}
__device__ __forceinline__ uint32_t packh2(float a, float b) {
    __half2 h = __floats2half2_rn(a, b);
    return *(uint32_t*)&h;
}

__device__ __forceinline__ void store_split_bf16(__nv_bfloat16* H, __nv_bfloat16* L,
                                                 size_t idx, float v0, float v1) {
    __nv_bfloat16 h0 = __float2bfloat16(v0), h1 = __float2bfloat16(v1);
    __nv_bfloat16 l0 = __float2bfloat16(v0 - __bfloat162float(h0));
    __nv_bfloat16 l1 = __float2bfloat16(v1 - __bfloat162float(h1));
    *(__nv_bfloat162*)(H + idx) = __halves2bfloat162(h0, h1);
    *(__nv_bfloat162*)(L + idx) = __halves2bfloat162(l0, l1);
}
__device__ __forceinline__ void store_split_f16(__half* H, __half* L,
                                                size_t idx, float v0, float v1) {
    __half h0 = __float2half(v0), h1 = __float2half(v1);
    __half l0 = __float2half(v0 - __half2float(h0));
    __half l1 = __float2half(v1 - __half2float(h1));
    *(__half2*)(H + idx) = __halves2half2(h0, h1);
    *(__half2*)(L + idx) = __halves2half2(l0, l1);
}

// Prepass: fp32 -> fp16 (single)
__global__ __launch_bounds__(256) void convert_f16(const float4* __restrict__ src,
                                                   uint2* __restrict__ dst, int n4)
{
    for (int i = blockIdx.x * blockDim.x + threadIdx.x; i < n4; i += gridDim.x * blockDim.x) {
        float4 v = src[i];
        uint2 o;
        o.x = packh2(v.x, v.y);
        o.y = packh2(v.z, v.w);
        dst[i] = o;
    }
}
// Prepass: fp32 -> (x*256) fp16 hi/lo
__global__ __launch_bounds__(256) void convert_split_f16s(const float4* __restrict__ src,
                                                          uint2* __restrict__ hi,
                                                          uint2* __restrict__ lo, int n4)
{
    for (int i = blockIdx.x * blockDim.x + threadIdx.x; i < n4; i += gridDim.x * blockDim.x) {
        float4 v = src[i];
        v.x *= WSC; v.y *= WSC; v.z *= WSC; v.w *= WSC;
        __half h0 = __float2half(v.x), h1 = __float2half(v.y);
        __half h2 = __float2half(v.z), h3 = __float2half(v.w);
        __half l0 = __float2half(v.x - __half2float(h0));
        __half l1 = __float2half(v.y - __half2float(h1));
        __half l2 = __float2half(v.z - __half2float(h2));
        __half l3 = __float2half(v.w - __half2float(h3));
        uint2 H, L;
        __half2 t;
        t = __halves2half2(h0, h1); H.x = *(uint32_t*)&t;
        t = __halves2half2(h2, h3); H.y = *(uint32_t*)&t;
        t = __halves2half2(l0, l1); L.x = *(uint32_t*)&t;
        t = __halves2half2(l2, l3); L.y = *(uint32_t*)&t;
        hi[i] = H;
        lo[i] = L;
    }
}

// Tile offset: two 64B k-rows packed per 128B SMEM line, SW128 swizzle (GEMM tiles).
__device__ __forceinline__ uint32_t toff(int r, int c) {
    uint32_t o = ((uint32_t)(r >> 1) << 7) | ((uint32_t)(r & 1) << 6) | ((uint32_t)c << 4);
    return o ^ ((o >> 3) & 0x70);
}
// 128B-row SW128 swizzle (attention tiles)
__device__ __forceinline__ uint32_t soff(int r, int c) {
    uint32_t o = (uint32_t)r * 128 + (uint32_t)c * 16;
    return o ^ ((o >> 3) & 0x70);
}

// ---------------------------------------------------------------------------
// fp16 GEMM NT, asymmetric split: C[m,n] = (1/256) * sum_k A[m,k]*(Bh+Bl)[n,k]
// 128x128 CTA tile, BK=32, 8 warps (2m x 4n), warp tile 64x32.
// 3-stage cp.async pipeline, ONE __syncthreads per chunk.
// Buffer: A 8K | Bh 8K | Bl 8K = 24KB, x3 stages = 72KB.
// MODE 0: C = fp32 out (proj).  MODE 1: QKV scatter epilogue.
// ---------------------------------------------------------------------------
#define GSMEM (3 * 24576)

template <int MODE>
__global__ __launch_bounds__(256) void gemm_f16(const __half* __restrict__ A,
                                                const __half* __restrict__ Bh,
                                                const __half* __restrict__ Bl,
                                                float* __restrict__ C, int N)
{
    extern __shared__ __align__(1024) uint8_t smem[];
    const uint32_t sb = smem_u32(smem);

    const int tid = threadIdx.x;
    const int lane = tid & 31;
    const int wid = tid >> 5;
    const int wm = wid & 1;
    const int wn = wid >> 1;
    const int bm = blockIdx.y * 128;
    const int bn = blockIdx.x * 128;

    const int idx0 = tid * 2;
    const int m0 = idx0 >> 2, c0 = idx0 & 3;
    const int m1 = (idx0 + 1) >> 2, c1 = (idx0 + 1) & 3;
    const uint32_t so0 = toff(m0, c0);
    const uint32_t so1 = toff(m1, c1);

    const __half* pA0 = A + (size_t)(bm + m0) * 1024 + c0 * 8;
    const __half* pA1 = A + (size_t)(bm + m1) * 1024 + c1 * 8;
    const __half* pBh0 = Bh + (size_t)(bn + m0) * 1024 + c0 * 8;
    const __half* pBh1 = Bh + (size_t)(bn + m1) * 1024 + c1 * 8;
    const __half* pBl0 = Bl + (size_t)(bn + m0) * 1024 + c0 * 8;
    const __half* pBl1 = Bl + (size_t)(bn + m1) * 1024 + c1 * 8;

    const int a_row = wm * 64 + (lane & 15);
    const int a_k16 = lane >> 4;
    const int b_row = wn * 32 + (lane & 7) + ((lane >> 4) & 1) * 8;
    const int b_k16 = (lane >> 3) & 1;

    float acc[4][4][4] = {};

    // prologue: stage chunks 0 and 1
#pragma unroll
    for (int p = 0; p < 2; p++) {
        const uint32_t s = sb + p * 24576;
        const int ko = p * 32;
        cp16(s + so0, pA0 + ko);           cp16(s + so1, pA1 + ko);
        cp16(s + 8192 + so0, pBh0 + ko);   cp16(s + 8192 + so1, pBh1 + ko);
        cp16(s + 16384 + so0, pBl0 + ko);  cp16(s + 16384 + so1, pBl1 + ko);
        CP_COMMIT();
    }

    int slot = 0, nslot = 2;
    for (int kc = 0; kc < 32; kc++) {
        if (kc < 31) CP_WAIT(1); else CP_WAIT(0);
        __syncthreads();

        // issue loads for chunk kc+2 into nslot (safe: all warps finished reading
        // nslot == slot of chunk kc-1 before the barrier above)
        if (kc + 2 < 32) {
            const uint32_t s = sb + nslot * 24576;
            const int ko = (kc + 2) * 32;
            cp16(s + so0, pA0 + ko);           cp16(s + so1, pA1 + ko);
            cp16(s + 8192 + so0, pBh0 + ko);   cp16(s + 8192 + so1, pBh1 + ko);
            cp16(s + 16384 + so0, pBl0 + ko);  cp16(s + 16384 + so1, pBl1 + ko);
            CP_COMMIT();
        }

        const uint32_t buf = sb + slot * 24576;
#pragma unroll
        for (int ks = 0; ks < 2; ks++) {
            uint32_t a[4][4], bh[4][2], bl[4][2];
#pragma unroll
            for (int mt = 0; mt < 4; mt++) {
                const uint32_t off = toff(a_row + mt * 16, ks * 2 + a_k16);
                ldm_x4(a[mt], buf + off);
            }
#pragma unroll
            for (int nt2 = 0; nt2 < 2; nt2++) {
                const uint32_t off = toff(b_row + nt2 * 16, ks * 2 + b_k16);
                uint32_t rh[4], rl[4];
                ldm_x4(rh, buf + 8192 + off);
                ldm_x4(rl, buf + 16384 + off);
                bh[nt2 * 2][0] = rh[0]; bh[nt2 * 2][1] = rh[1];
                bh[nt2 * 2 + 1][0] = rh[2]; bh[nt2 * 2 + 1][1] = rh[3];
                bl[nt2 * 2][0] = rl[0]; bl[nt2 * 2][1] = rl[1];
                bl[nt2 * 2 + 1][0] = rl[2]; bl[nt2 * 2 + 1][1] = rl[3];
            }
#pragma unroll
            for (int mt = 0; mt < 4; mt++)
#pragma unroll
                for (int nt = 0; nt < 4; nt++) {
                    mma_f16(acc[mt][nt], a[mt], bh[nt]);
                    mma_f16(acc[mt][nt], a[mt], bl[nt]);
                }
        }
        slot = (slot + 1) % 3;
        nslot = (nslot + 1) % 3;
    }

    if (MODE == 0) {
#pragma unroll
        for (int mt = 0; mt < 4; mt++) {
            const int r0 = bm + wm * 64 + mt * 16 + (lane >> 2);
#pragma unroll
            for (int nt = 0; nt < 4; nt++) {
                const int c = bn + wn * 32 + nt * 8 + (lane & 3) * 2;
                float2 v0 = {acc[mt][nt][0] * WSCI, acc[mt][nt][1] * WSCI};
                float2 v1 = {acc[mt][nt][2] * WSCI, acc[mt][nt][3] * WSCI};
                *(float2*)(C + (size_t)r0 * N + c) = v0;
                *(float2*)(C + (size_t)(r0 + 8) * N + c) = v1;
            }
        }
    } else {
        // QKV scatter: row=token, col in [0,3072)
#pragma unroll
        for (int mt = 0; mt < 4; mt++) {
            const int row = bm + wm * 64 + mt * 16 + (lane >> 2);
#pragma unroll
            for (int nt = 0; nt < 4; nt++) {
                const int c = bn + wn * 32 + nt * 8 + (lane & 3) * 2;
                const int which = c >> 10;
                const int hh = (c >> 6) & 15;
                const int d = c & 63;
#pragma unroll
                for (int half = 0; half < 2; half++) {
                    const int r = row + half * 8;
                    const int bb = r >> 11;
                    const int s = r & 2047;
                    const size_t idx = (((size_t)(bb * 16 + hh)) * SS + s) * 64 + d;
                    float v0 = acc[mt][nt][half * 2] * WSCI;
                    float v1 = acc[mt][nt][half * 2 + 1] * WSCI;
                    if (which == 0) {
                        store_split_bf16(g_qh, g_ql, idx, v0 * QSCALE, v1 * QSCALE);
                    } else if (which == 1) {
                        store_split_bf16(g_kh, g_kl, idx, v0, v1);
                    } else {
                        store_split_f16(g_vh, g_vl, idx, v0, v1);
                    }
                }
            }
        }
    }
}

// ---------------------------------------------------------------------------
// Flash attention on mma.sync (validated in R5/R6).
// SMEM: Qh 16K | Ql 16K | K bufs 2x(8K+8K) | V bufs 2x(8K+8K) = 96KB.
// ---------------------------------------------------------------------------
#define ASMEM 98304

__device__ __forceinline__ void attn_load_kv(uint32_t sb, size_t bh, int kt, int buf, int tid)
{
#pragma unroll
    for (int i = 0; i < 8; i++) {
        const int id = tid + 256 * i;
        const int t = id >> 9;        // 0 Kh,1 Kl,2 Vh,3 Vl
        const int w = id & 511;
        const int r = w >> 3, c = w & 7;
        const uint32_t swz = soff(r, c);
        const size_t gidx = (bh * SS + (size_t)kt * 64 + r) * 64 + c * 8;
        uint32_t dst;
        const void* src;
        if (t == 0)      { dst = sb + 32768 + buf * 16384 + swz;        src = g_kh + gidx; }
        else if (t == 1) { dst = sb + 32768 + buf * 16384 + 8192 + swz; src = g_kl + gidx; }
        else if (t == 2) { dst = sb + 65536 + buf * 16384 + swz;        src = g_vh + gidx; }
        else             { dst = sb + 65536 + buf * 16384 + 8192 + swz; src = g_vl + gidx; }
        cp16(dst, src);
    }
}

__global__ __launch_bounds__(256) void attn_mma()
{
    extern __shared__ __align__(1024) uint8_t sm[];
    const uint32_t sb = smem_u32(sm);
    const int qt = (int)gridDim.x - 1 - (int)blockIdx.x;  // heavy tiles first
    const int h = blockIdx.y;
    const int b = blockIdx.z;
    const int tid = threadIdx.x;
    const int lane = tid & 31;
    const int wid = tid >> 5;
    const size_t bh = (size_t)(b * HH + h);
    const int nkt = 2 * qt + 2;

#pragma unroll
    for (int i = 0; i < 8; i++) {
        const int id = tid + 256 * i;
        const int t = id >> 10;       // 0 Qh, 1 Ql
        const int w = id & 1023;
        const int r = w >> 3, c = w & 7;
        const uint32_t dst = sb + t * 16384 + soff(r, c);
        const size_t gidx = (bh * SS + (size_t)qt * 128 + r) * 64 + c * 8;
        cp16(dst, t == 0 ? (const void*)(g_qh + gidx) : (const void*)(g_ql + gidx));
    }
    attn_load_kv(sb, bh, 0, 0, tid);
    CP_COMMIT();
    attn_load_kv(sb, bh, 1, 1, tid);
    CP_COMMIT();

    float m1 = -CUDART_INF_F, m2 = -CUDART_INF_F;
    float o[8][4] = {};
    float lac[4] = {};
    const uint32_t ones2[2] = {0x3C003C00u, 0x3C003C00u};

    const int rg1 = qt * 128 + wid * 16 + (lane >> 2);

    for (int kt = 0; kt < nkt; kt++) {
        CP_WAIT(1);
        __syncthreads();

        const uint32_t kb = sb + 32768 + (kt & 1) * 16384;
        const uint32_t vb = sb + 65536 + (kt & 1) * 16384;

        const bool skipall = (kt == 2 * qt + 1) && (wid < 4);
        if (!skipall) {
            float s[8][4];
#pragma unroll
            for (int nt = 0; nt < 8; nt++)
#pragma unroll
                for (int j = 0; j < 4; j++) s[nt][j] = 0.f;

#pragma unroll
            for (int ks = 0; ks < 4; ks++) {
                uint32_t qa[4], ql[4];
                const uint32_t offA = soff(wid * 16 + (lane & 15), ks * 2 + (lane >> 4));
                ldm_x4(qa, sb + offA);
                ldm_x4(ql, sb + 16384 + offA);
#pragma unroll
                for (int nb = 0; nb < 4; nb++) {
                    const uint32_t offB = soff(nb * 16 + (lane & 7) + ((lane >> 4) & 1) * 8,
                                               ks * 2 + ((lane >> 3) & 1));
                    uint32_t rh[4], rl[4];
                    ldm_x4(rh, kb + offB);
                    ldm_x4(rl, kb + 8192 + offB);
                    mma_bf16(s[nb * 2], qa, rh);
                    mma_bf16(s[nb * 2], qa, rl);
                    mma_bf16(s[nb * 2], ql, rh);
                    mma_bf16(s[nb * 2 + 1], qa, rh + 2);
                    mma_bf16(s[nb * 2 + 1], qa, rl + 2);
                    mma_bf16(s[nb * 2 + 1], ql, rh + 2);
                }
            }

            const bool domask = (kt == 2 * qt && wid < 4) || (kt == 2 * qt + 1 && wid >= 4);
            if (domask) {
#pragma unroll
                for (int nt = 0; nt < 8; nt++) {
                    const int cg = kt * 64 + nt * 8 + (lane & 3) * 2;
#pragma unroll
                    for (int j = 0; j < 4; j++) {
                        const int col = cg + (j & 1);
                        const int row = rg1 + ((j >> 1) << 3);
                        if (col > row) s[nt][j] = -1e30f;
                    }
                }
            }

            float t1 = -CUDART_INF_F, t2 = -CUDART_INF_F;
#pragma unroll
            for (int nt = 0; nt < 8; nt++) {
                t1 = fmaxf(t1, fmaxf(s[nt][0], s[nt][1]));
                t2 = fmaxf(t2, fmaxf(s[nt][2], s[nt][3]));
            }
            t1 = fmaxf(t1, __shfl_xor_sync(0xffffffffu, t1, 1));
            t1 = fmaxf(t1, __shfl_xor_sync(0xffffffffu, t1, 2));
            t2 = fmaxf(t2, __shfl_xor_sync(0xffffffffu, t2, 1));
            t2 = fmaxf(t2, __shfl_xor_sync(0xffffffffu, t2, 2));
            const float mn1 = fmaxf(m1, t1);
            const float mn2 = fmaxf(m2, t2);
            const float cr1 = ex2f(m1 - mn1);
            const float cr2 = ex2f(m2 - mn2);
            m1 = mn1; m2 = mn2;

            uint32_t p1[8], p2[8];
#pragma unroll
            for (int nt = 0; nt < 8; nt++) {
                p1[nt] = packh2(ex2f(s[nt][0] - mn1), ex2f(s[nt][1] - mn1));
                p2[nt] = packh2(ex2f(s[nt][2] - mn2), ex2f(s[nt][3] - mn2));
            }
#pragma unroll
            for (int nt = 0; nt < 8; nt++) {
                o[nt][0] *= cr1; o[nt][1] *= cr1;
                o[nt][2] *= cr2; o[nt][3] *= cr2;
            }
            lac[0] *= cr1; lac[1] *= cr1; lac[2] *= cr2; lac[3] *= cr2;

#pragma unroll
            for (int ks = 0; ks < 4; ks++) {
                uint32_t A[4] = {p1[ks * 2], p2[ks * 2], p1[ks * 2 + 1], p2[ks * 2 + 1]};
#pragma unroll
                for (int nb = 0; nb < 4; nb++) {
                    const uint32_t offV = soff(ks * 16 + (lane & 15), nb * 2 + (lane >> 4));
                    uint32_t vh[4], vl[4];
                    ldm_x4_t(vh, vb + offV);
                    ldm_x4_t(vl, vb + 8192 + offV);
                    mma_f16(o[nb * 2], A, vh);
                    mma_f16(o[nb * 2], A, vl);
                    mma_f16(o[nb * 2 + 1], A, vh + 2);
                    mma_f16(o[nb * 2 + 1], A, vl + 2);
                }
                mma_f16(lac, A, ones2);
            }
        }

        __syncthreads();
        if (kt + 2 < nkt) attn_load_kv(sb, bh, kt + 2, kt & 1, tid);
        CP_COMMIT();
    }

    // epilogue: normalize, write single fp16 [token][1024]
    const float inv1 = 1.f / lac[0];
    const float inv2 = 1.f / lac[2];
    const size_t tok1 = (size_t)(b * SS + qt * 128 + wid * 16 + (lane >> 2));
#pragma unroll
    for (int nt = 0; nt < 8; nt++) {
        const int col = h * 64 + nt * 8 + (lane & 3) * 2;
        const uint32_t u1 = packh2(o[nt][0] * inv1, o[nt][1] * inv1);
        const uint32_t u2 = packh2(o[nt][2] * inv2, o[nt][3] * inv2);
        *(uint32_t*)(g_af + tok1 * 1024 + col) = u1;
        *(uint32_t*)(g_af + (tok1 + 8) * 1024 + col) = u2;
    }
}

// ---------------------------------------------------------------------------
extern "C" void kernel_launch(void* const* d_in, const int* in_sizes, int n_in,
                              void* d_out, int out_size)
{
    const float* x    = (const float*)d_in[0];  // [2,2048,1024]
    const float* wqkv = (const float*)d_in[1];  // [3072,1024]
    const float* wo   = (const float*)d_in[2];  // [1024,1024]
    float* out = (float*)d_out;                 // [2,2048,1024]

    __half *xf, *wh, *wl, *woh, *wol, *af;
    cudaGetSymbolAddress((void**)&xf, g_xf);
    cudaGetSymbolAddress((void**)&wh, g_wh);
    cudaGetSymbolAddress((void**)&wl, g_wl);
    cudaGetSymbolAddress((void**)&woh, g_woh);
    cudaGetSymbolAddress((void**)&wol, g_wol);
    cudaGetSymbolAddress((void**)&af, g_af);

    cudaFuncSetAttribute(gemm_f16<0>, cudaFuncAttributeMaxDynamicSharedMemorySize, GSMEM);
    cudaFuncSetAttribute(gemm_f16<1>, cudaFuncAttributeMaxDynamicSharedMemorySize, GSMEM);
    cudaFuncSetAttribute(attn_mma, cudaFuncAttributeMaxDynamicSharedMemorySize, ASMEM);

    // Prepass conversions
    convert_f16<<<512, 256>>>((const float4*)x, (uint2*)xf, 4096 * 1024 / 4);
    convert_split_f16s<<<512, 256>>>((const float4*)wqkv, (uint2*)wh, (uint2*)wl, 3072 * 1024 / 4);
    convert_split_f16s<<<256, 256>>>((const float4*)wo, (uint2*)woh, (uint2*)wol, 1024 * 1024 / 4);

    // QKV = x @ wqkv^T with scatter epilogue -> g_qh/ql/kh/kl/vh/vl
    gemm_f16<1><<<dim3(3072 / 128, 4096 / 128), 256, GSMEM>>>(xf, wh, wl, nullptr, 3072);

    // Attention -> g_af (fp16)
    attn_mma<<<dim3(SS / 128, HH, BB), 256, ASMEM>>>();

    // out = attn @ wo^T
    gemm_f16<0><<<dim3(1024 / 128, 4096 / 128), 256, GSMEM>>>(af, woh, wol, out, 1024);
}

// round 9
// speedup vs baseline: 1.0976x; 1.0976x over previous
#include <cuda_runtime.h>
#include <cuda_bf16.h>
#include <cuda_fp16.h>
#include <math.h>
#include <math_constants.h>
#include <cstdint>

// Problem constants
#define BB 2
#define SS 2048
#define DD 1024
#define HH 16
#define DHH 64

// log2(e)/8  (folded into Q so softmax is pure 2^x)
#define QSCALE 0.18033688011112042f
#define WSC 256.0f
#define WSCI (1.0f / 256.0f)

// ---------------- device scratch (no cudaMalloc allowed) ----------------
__device__ __align__(16) __half g_xf[4096 * 1024];          // x, fp16
__device__ __align__(16) __half g_wh[3072 * 1024];          // wqkv*256 hi
__device__ __align__(16) __half g_wl[3072 * 1024];          // wqkv*256 lo
__device__ __align__(16) __half g_woh[1024 * 1024];         // wo*256 hi
__device__ __align__(16) __half g_wol[1024 * 1024];         // wo*256 lo
__device__ __align__(16) __half g_af[4096 * 1024];          // attn out, fp16

// Q,K (bf16 hi/lo) and V (fp16 hi/lo) in [b][h][s][d] layout
__device__ __align__(16) __nv_bfloat16 g_qh[BB * HH * SS * DHH];
__device__ __align__(16) __nv_bfloat16 g_ql[BB * HH * SS * DHH];
__device__ __align__(16) __nv_bfloat16 g_kh[BB * HH * SS * DHH];
__device__ __align__(16) __nv_bfloat16 g_kl[BB * HH * SS * DHH];
__device__ __align__(16) __half       g_vh[BB * HH * SS * DHH];
__device__ __align__(16) __half       g_vl[BB * HH * SS * DHH];

// ============================ helpers ============================
__device__ __forceinline__ uint32_t smem_u32(const void* p) {
    uint32_t a;
    asm("{ .reg .u64 t; cvta.to.shared.u64 t, %1; cvt.u32.u64 %0, t; }" : "=r"(a) : "l"(p));
    return a;
}

__device__ __forceinline__ void ldm_x4(uint32_t* r, uint32_t addr) {
    asm volatile("ldmatrix.sync.aligned.m8n8.x4.shared.b16 {%0,%1,%2,%3}, [%4];"
                 : "=r"(r[0]), "=r"(r[1]), "=r"(r[2]), "=r"(r[3]) : "r"(addr));
}
__device__ __forceinline__ void ldm_x4_t(uint32_t* r, uint32_t addr) {
    asm volatile("ldmatrix.sync.aligned.m8n8.x4.trans.shared.b16 {%0,%1,%2,%3}, [%4];"
                 : "=r"(r[0]), "=r"(r[1]), "=r"(r[2]), "=r"(r[3]) : "r"(addr));
}

__device__ __forceinline__ void mma_bf16(float* d, const uint32_t* a, const uint32_t* b) {
    asm volatile(
        "mma.sync.aligned.m16n8k16.row.col.f32.bf16.bf16.f32 "
        "{%0,%1,%2,%3}, {%4,%5,%6,%7}, {%8,%9}, {%0,%1,%2,%3};"
        : "+f"(d[0]), "+f"(d[1]), "+f"(d[2]), "+f"(d[3])
        : "r"(a[0]), "r"(a[1]), "r"(a[2]), "r"(a[3]), "r"(b[0]), "r"(b[1]));
}
__device__ __forceinline__ void mma_f16(float* d, const uint32_t* a, const uint32_t* b) {
    asm volatile(
        "mma.sync.aligned.m16n8k16.row.col.f32.f16.f16.f32 "
        "{%0,%1,%2,%3}, {%4,%5,%6,%7}, {%8,%9}, {%0,%1,%2,%3};"
        : "+f"(d[0]), "+f"(d[1]), "+f"(d[2]), "+f"(d[3])
        : "r"(a[0]), "r"(a[1]), "r"(a[2]), "r"(a[3]), "r"(b[0]), "r"(b[1]));
}

__device__ __forceinline__ void cp16(uint32_t dst, const void* src) {
    asm volatile("cp.async.cg.shared.global [%0], [%1], 16;" :: "r"(dst), "l"(src));
}
#define CP_COMMIT() asm volatile("cp.async.commit_group;" ::: "memory")
#define CP_WAIT(n)  asm volatile("cp.async.wait_group %0;" :: "n"(n) : "memory")

__device__ __forceinline__ float ex2f(float x) {
    float y;
    asm("ex2.approx.ftz.f32 %0, %1;" : "=f"(y) : "f"(x));
    return y;
}
__device__ __forceinline__ uint32_t packh2(float a, float b) {
    __half2 h = __floats2half2_rn(a, b);
    return *(uint32_t*)&h;
}

__device__ __forceinline__ void store_split_bf16(__nv_bfloat16* H, __nv_bfloat16* L,
                                                 size_t idx, float v0, float v1) {
    __nv_bfloat16 h0 = __float2bfloat16(v0), h1 = __float2bfloat16(v1);
    __nv_bfloat16 l0 = __float2bfloat16(v0 - __bfloat162float(h0));
    __nv_bfloat16 l1 = __float2bfloat16(v1 - __bfloat162float(h1));
    *(__nv_bfloat162*)(H + idx) = __halves2bfloat162(h0, h1);
    *(__nv_bfloat162*)(L + idx) = __halves2bfloat162(l0, l1);
}
__device__ __forceinline__ void store_split_f16(__half* H, __half* L,
                                                size_t idx, float v0, float v1) {
    __half h0 = __float2half(v0), h1 = __float2half(v1);
    __half l0 = __float2half(v0 - __half2float(h0));
    __half l1 = __float2half(v1 - __half2float(h1));
    *(__half2*)(H + idx) = __halves2half2(h0, h1);
    *(__half2*)(L + idx) = __halves2half2(l0, l1);
}

// Prepass: fp32 -> fp16 (single)
__global__ __launch_bounds__(256) void convert_f16(const float4* __restrict__ src,
                                                   uint2* __restrict__ dst, int n4)
{
    for (int i = blockIdx.x * blockDim.x + threadIdx.x; i < n4; i += gridDim.x * blockDim.x) {
        float4 v = src[i];
        uint2 o;
        o.x = packh2(v.x, v.y);
        o.y = packh2(v.z, v.w);
        dst[i] = o;
    }
}
// Prepass: fp32 -> (x*256) fp16 hi/lo
__global__ __launch_bounds__(256) void convert_split_f16s(const float4* __restrict__ src,
                                                          uint2* __restrict__ hi,
                                                          uint2* __restrict__ lo, int n4)
{
    for (int i = blockIdx.x * blockDim.x + threadIdx.x; i < n4; i += gridDim.x * blockDim.x) {
        float4 v = src[i];
        v.x *= WSC; v.y *= WSC; v.z *= WSC; v.w *= WSC;
        __half h0 = __float2half(v.x), h1 = __float2half(v.y);
        __half h2 = __float2half(v.z), h3 = __float2half(v.w);
        __half l0 = __float2half(v.x - __half2float(h0));
        __half l1 = __float2half(v.y - __half2float(h1));
        __half l2 = __float2half(v.z - __half2float(h2));
        __half l3 = __float2half(v.w - __half2float(h3));
        uint2 H, L;
        __half2 t;
        t = __halves2half2(h0, h1); H.x = *(uint32_t*)&t;
        t = __halves2half2(h2, h3); H.y = *(uint32_t*)&t;
        t = __halves2half2(l0, l1); L.x = *(uint32_t*)&t;
        t = __halves2half2(l2, l3); L.y = *(uint32_t*)&t;
        hi[i] = H;
        lo[i] = L;
    }
}

// Tile offset: two 64B k-rows packed per 128B SMEM line, SW128 swizzle (GEMM tiles).
__device__ __forceinline__ uint32_t toff(int r, int c) {
    uint32_t o = ((uint32_t)(r >> 1) << 7) | ((uint32_t)(r & 1) << 6) | ((uint32_t)c << 4);
    return o ^ ((o >> 3) & 0x70);
}
// 128B-row SW128 swizzle (attention tiles)
__device__ __forceinline__ uint32_t soff(int r, int c) {
    uint32_t o = (uint32_t)r * 128 + (uint32_t)c * 16;
    return o ^ ((o >> 3) & 0x70);
}

// ---------------------------------------------------------------------------
// fp16 GEMM NT, asymmetric split: C[m,n] = (1/256) * sum_k A[m,k]*(Bh+Bl)[n,k]
// 128x128 CTA tile, BK=32, 8 warps (2m x 4n), warp tile 64x32.
// 3-stage cp.async pipeline, ONE __syncthreads per chunk, 2 CTAs/SM enforced.
// Buffer: A 8K | Bh 8K | Bl 8K = 24KB, x3 stages = 72KB.
// MODE 0: C = fp32 out (proj).  MODE 1: QKV scatter epilogue.
// ---------------------------------------------------------------------------
#define GSMEM (3 * 24576)

template <int MODE>
__global__ __launch_bounds__(256, 2) void gemm_f16(const __half* __restrict__ A,
                                                   const __half* __restrict__ Bh,
                                                   const __half* __restrict__ Bl,
                                                   float* __restrict__ C, int N)
{
    extern __shared__ __align__(1024) uint8_t smem[];
    const uint32_t sb = smem_u32(smem);

    const int tid = threadIdx.x;
    const int lane = tid & 31;
    const int wid = tid >> 5;
    const int wm = wid & 1;
    const int wn = wid >> 1;
    const int bm = blockIdx.y * 128;
    const int bn = blockIdx.x * 128;

    // each thread loads one contiguous 32B segment: row m0, chunks c0 and c0+1
    const int m0 = tid >> 1;
    const int c0 = (tid & 1) * 2;
    const uint32_t so0 = toff(m0, c0);
    const uint32_t so1 = toff(m0, c0 + 1);

    const __half* pA  = A  + (size_t)(bm + m0) * 1024 + c0 * 8;
    const __half* pBh = Bh + (size_t)(bn + m0) * 1024 + c0 * 8;
    const __half* pBl = Bl + (size_t)(bn + m0) * 1024 + c0 * 8;

    const int a_row = wm * 64 + (lane & 15);
    const int a_k16 = lane >> 4;
    const int b_row = wn * 32 + (lane & 7) + ((lane >> 4) & 1) * 8;
    const int b_k16 = (lane >> 3) & 1;

    float acc[4][4][4] = {};

    // prologue: stage chunks 0 and 1
#pragma unroll
    for (int p = 0; p < 2; p++) {
        const uint32_t s = sb + p * 24576;
        const int ko = p * 32;
        cp16(s + so0, pA + ko);           cp16(s + so1, pA + ko + 8);
        cp16(s + 8192 + so0, pBh + ko);   cp16(s + 8192 + so1, pBh + ko + 8);
        cp16(s + 16384 + so0, pBl + ko);  cp16(s + 16384 + so1, pBl + ko + 8);
        CP_COMMIT();
    }

    int slot = 0, nslot = 2;
    for (int kc = 0; kc < 32; kc++) {
        if (kc < 31) CP_WAIT(1); else CP_WAIT(0);
        __syncthreads();

        // issue loads for chunk kc+2 into nslot
        if (kc + 2 < 32) {
            const uint32_t s = sb + nslot * 24576;
            const int ko = (kc + 2) * 32;
            cp16(s + so0, pA + ko);           cp16(s + so1, pA + ko + 8);
            cp16(s + 8192 + so0, pBh + ko);   cp16(s + 8192 + so1, pBh + ko + 8);
            cp16(s + 16384 + so0, pBl + ko);  cp16(s + 16384 + so1, pBl + ko + 8);
            CP_COMMIT();
        }

        const uint32_t buf = sb + slot * 24576;
#pragma unroll
        for (int ks = 0; ks < 2; ks++) {
            uint32_t a[4][4], bh[4][2], bl[4][2];
#pragma unroll
            for (int mt = 0; mt < 4; mt++) {
                const uint32_t off = toff(a_row + mt * 16, ks * 2 + a_k16);
                ldm_x4(a[mt], buf + off);
            }
#pragma unroll
            for (int nt2 = 0; nt2 < 2; nt2++) {
                const uint32_t off = toff(b_row + nt2 * 16, ks * 2 + b_k16);
                uint32_t rh[4], rl[4];
                ldm_x4(rh, buf + 8192 + off);
                ldm_x4(rl, buf + 16384 + off);
                bh[nt2 * 2][0] = rh[0]; bh[nt2 * 2][1] = rh[1];
                bh[nt2 * 2 + 1][0] = rh[2]; bh[nt2 * 2 + 1][1] = rh[3];
                bl[nt2 * 2][0] = rl[0]; bl[nt2 * 2][1] = rl[1];
                bl[nt2 * 2 + 1][0] = rl[2]; bl[nt2 * 2 + 1][1] = rl[3];
            }
#pragma unroll
            for (int mt = 0; mt < 4; mt++)
#pragma unroll
                for (int nt = 0; nt < 4; nt++) {
                    mma_f16(acc[mt][nt], a[mt], bh[nt]);
                    mma_f16(acc[mt][nt], a[mt], bl[nt]);
                }
        }
        slot = (slot == 2) ? 0 : slot + 1;
        nslot = (nslot == 2) ? 0 : nslot + 1;
    }

    if (MODE == 0) {
#pragma unroll
        for (int mt = 0; mt < 4; mt++) {
            const int r0 = bm + wm * 64 + mt * 16 + (lane >> 2);
#pragma unroll
            for (int nt = 0; nt < 4; nt++) {
                const int c = bn + wn * 32 + nt * 8 + (lane & 3) * 2;
                float2 v0 = {acc[mt][nt][0] * WSCI, acc[mt][nt][1] * WSCI};
                float2 v1 = {acc[mt][nt][2] * WSCI, acc[mt][nt][3] * WSCI};
                *(float2*)(C + (size_t)r0 * N + c) = v0;
                *(float2*)(C + (size_t)(r0 + 8) * N + c) = v1;
            }
        }
    } else {
        // QKV scatter: row=token, col in [0,3072)
#pragma unroll
        for (int mt = 0; mt < 4; mt++) {
            const int row = bm + wm * 64 + mt * 16 + (lane >> 2);
#pragma unroll
            for (int nt = 0; nt < 4; nt++) {
                const int c = bn + wn * 32 + nt * 8 + (lane & 3) * 2;
                const int which = c >> 10;
                const int hh = (c >> 6) & 15;
                const int d = c & 63;
#pragma unroll
                for (int half = 0; half < 2; half++) {
                    const int r = row + half * 8;
                    const int bb = r >> 11;
                    const int s = r & 2047;
                    const size_t idx = (((size_t)(bb * 16 + hh)) * SS + s) * 64 + d;
                    float v0 = acc[mt][nt][half * 2] * WSCI;
                    float v1 = acc[mt][nt][half * 2 + 1] * WSCI;
                    if (which == 0) {
                        store_split_bf16(g_qh, g_ql, idx, v0 * QSCALE, v1 * QSCALE);
                    } else if (which == 1) {
                        store_split_bf16(g_kh, g_kl, idx, v0, v1);
                    } else {
                        store_split_f16(g_vh, g_vl, idx, v0, v1);
                    }
                }
            }
        }
    }
}

// ---------------------------------------------------------------------------
// Flash attention on mma.sync (validated in R5/R6).
// SMEM: Qh 16K | Ql 16K | K bufs 2x(8K+8K) | V bufs 2x(8K+8K) = 96KB.
// ---------------------------------------------------------------------------
#define ASMEM 98304

__device__ __forceinline__ void attn_load_kv(uint32_t sb, size_t bh, int kt, int buf, int tid)
{
#pragma unroll
    for (int i = 0; i < 8; i++) {
        const int id = tid + 256 * i;
        const int t = id >> 9;        // 0 Kh,1 Kl,2 Vh,3 Vl
        const int w = id & 511;
        const int r = w >> 3, c = w & 7;
        const uint32_t swz = soff(r, c);
        const size_t gidx = (bh * SS + (size_t)kt * 64 + r) * 64 + c * 8;
        uint32_t dst;
        const void* src;
        if (t == 0)      { dst = sb + 32768 + buf * 16384 + swz;        src = g_kh + gidx; }
        else if (t == 1) { dst = sb + 32768 + buf * 16384 + 8192 + swz; src = g_kl + gidx; }
        else if (t == 2) { dst = sb + 65536 + buf * 16384 + swz;        src = g_vh + gidx; }
        else             { dst = sb + 65536 + buf * 16384 + 8192 + swz; src = g_vl + gidx; }
        cp16(dst, src);
    }
}

__global__ __launch_bounds__(256) void attn_mma()
{
    extern __shared__ __align__(1024) uint8_t sm[];
    const uint32_t sb = smem_u32(sm);
    const int qt = (int)gridDim.x - 1 - (int)blockIdx.x;  // heavy tiles first
    const int h = blockIdx.y;
    const int b = blockIdx.z;
    const int tid = threadIdx.x;
    const int lane = tid & 31;
    const int wid = tid >> 5;
    const size_t bh = (size_t)(b * HH + h);
    const int nkt = 2 * qt + 2;

#pragma unroll
    for (int i = 0; i < 8; i++) {
        const int id = tid + 256 * i;
        const int t = id >> 10;       // 0 Qh, 1 Ql
        const int w = id & 1023;
        const int r = w >> 3, c = w & 7;
        const uint32_t dst = sb + t * 16384 + soff(r, c);
        const size_t gidx = (bh * SS + (size_t)qt * 128 + r) * 64 + c * 8;
        cp16(dst, t == 0 ? (const void*)(g_qh + gidx) : (const void*)(g_ql + gidx));
    }
    attn_load_kv(sb, bh, 0, 0, tid);
    CP_COMMIT();
    attn_load_kv(sb, bh, 1, 1, tid);
    CP_COMMIT();

    float m1 = -CUDART_INF_F, m2 = -CUDART_INF_F;
    float o[8][4] = {};
    float lac[4] = {};
    const uint32_t ones2[2] = {0x3C003C00u, 0x3C003C00u};

    const int rg1 = qt * 128 + wid * 16 + (lane >> 2);

    for (int kt = 0; kt < nkt; kt++) {
        CP_WAIT(1);
        __syncthreads();

        const uint32_t kb = sb + 32768 + (kt & 1) * 16384;
        const uint32_t vb = sb + 65536 + (kt & 1) * 16384;

        const bool skipall = (kt == 2 * qt + 1) && (wid < 4);
        if (!skipall) {
            float s[8][4];
#pragma unroll
            for (int nt = 0; nt < 8; nt++)
#pragma unroll
                for (int j = 0; j < 4; j++) s[nt][j] = 0.f;

#pragma unroll
            for (int ks = 0; ks < 4; ks++) {
                uint32_t qa[4], ql[4];
                const uint32_t offA = soff(wid * 16 + (lane & 15), ks * 2 + (lane >> 4));
                ldm_x4(qa, sb + offA);
                ldm_x4(ql, sb + 16384 + offA);
#pragma unroll
                for (int nb = 0; nb < 4; nb++) {
                    const uint32_t offB = soff(nb * 16 + (lane & 7) + ((lane >> 4) & 1) * 8,
                                               ks * 2 + ((lane >> 3) & 1));
                    uint32_t rh[4], rl[4];
                    ldm_x4(rh, kb + offB);
                    ldm_x4(rl, kb + 8192 + offB);
                    mma_bf16(s[nb * 2], qa, rh);
                    mma_bf16(s[nb * 2], qa, rl);
                    mma_bf16(s[nb * 2], ql, rh);
                    mma_bf16(s[nb * 2 + 1], qa, rh + 2);
                    mma_bf16(s[nb * 2 + 1], qa, rl + 2);
                    mma_bf16(s[nb * 2 + 1], ql, rh + 2);
                }
            }

            const bool domask = (kt == 2 * qt && wid < 4) || (kt == 2 * qt + 1 && wid >= 4);
            if (domask) {
#pragma unroll
                for (int nt = 0; nt < 8; nt++) {
                    const int cg = kt * 64 + nt * 8 + (lane & 3) * 2;
#pragma unroll
                    for (int j = 0; j < 4; j++) {
                        const int col = cg + (j & 1);
                        const int row = rg1 + ((j >> 1) << 3);
                        if (col > row) s[nt][j] = -1e30f;
                    }
                }
            }

            float t1 = -CUDART_INF_F, t2 = -CUDART_INF_F;
#pragma unroll
            for (int nt = 0; nt < 8; nt++) {
                t1 = fmaxf(t1, fmaxf(s[nt][0], s[nt][1]));
                t2 = fmaxf(t2, fmaxf(s[nt][2], s[nt][3]));
            }
            t1 = fmaxf(t1, __shfl_xor_sync(0xffffffffu, t1, 1));
            t1 = fmaxf(t1, __shfl_xor_sync(0xffffffffu, t1, 2));
            t2 = fmaxf(t2, __shfl_xor_sync(0xffffffffu, t2, 1));
            t2 = fmaxf(t2, __shfl_xor_sync(0xffffffffu, t2, 2));
            const float mn1 = fmaxf(m1, t1);
            const float mn2 = fmaxf(m2, t2);
            const float cr1 = ex2f(m1 - mn1);
            const float cr2 = ex2f(m2 - mn2);
            m1 = mn1; m2 = mn2;

            uint32_t p1[8], p2[8];
#pragma unroll
            for (int nt = 0; nt < 8; nt++) {
                p1[nt] = packh2(ex2f(s[nt][0] - mn1), ex2f(s[nt][1] - mn1));
                p2[nt] = packh2(ex2f(s[nt][2] - mn2), ex2f(s[nt][3] - mn2));
            }
#pragma unroll
            for (int nt = 0; nt < 8; nt++) {
                o[nt][0] *= cr1; o[nt][1] *= cr1;
                o[nt][2] *= cr2; o[nt][3] *= cr2;
            }
            lac[0] *= cr1; lac[1] *= cr1; lac[2] *= cr2; lac[3] *= cr2;

#pragma unroll
            for (int ks = 0; ks < 4; ks++) {
                uint32_t A[4] = {p1[ks * 2], p2[ks * 2], p1[ks * 2 + 1], p2[ks * 2 + 1]};
#pragma unroll
                for (int nb = 0; nb < 4; nb++) {
                    const uint32_t offV = soff(ks * 16 + (lane & 15), nb * 2 + (lane >> 4));
                    uint32_t vh[4], vl[4];
                    ldm_x4_t(vh, vb + offV);
                    ldm_x4_t(vl, vb + 8192 + offV);
                    mma_f16(o[nb * 2], A, vh);
                    mma_f16(o[nb * 2], A, vl);
                    mma_f16(o[nb * 2 + 1], A, vh + 2);
                    mma_f16(o[nb * 2 + 1], A, vl + 2);
                }
                mma_f16(lac, A, ones2);
            }
        }

        __syncthreads();
        if (kt + 2 < nkt) attn_load_kv(sb, bh, kt + 2, kt & 1, tid);
        CP_COMMIT();
    }

    // epilogue: normalize, write single fp16 [token][1024]
    const float inv1 = 1.f / lac[0];
    const float inv2 = 1.f / lac[2];
    const size_t tok1 = (size_t)(b * SS + qt * 128 + wid * 16 + (lane >> 2));
#pragma unroll
    for (int nt = 0; nt < 8; nt++) {
        const int col = h * 64 + nt * 8 + (lane & 3) * 2;
        const uint32_t u1 = packh2(o[nt][0] * inv1, o[nt][1] * inv1);
        const uint32_t u2 = packh2(o[nt][2] * inv2, o[nt][3] * inv2);
        *(uint32_t*)(g_af + tok1 * 1024 + col) = u1;
        *(uint32_t*)(g_af + (tok1 + 8) * 1024 + col) = u2;
    }
}

// ---------------------------------------------------------------------------
extern "C" void kernel_launch(void* const* d_in, const int* in_sizes, int n_in,
                              void* d_out, int out_size)
{
    const float* x    = (const float*)d_in[0];  // [2,2048,1024]
    const float* wqkv = (const float*)d_in[1];  // [3072,1024]
    const float* wo   = (const float*)d_in[2];  // [1024,1024]
    float* out = (float*)d_out;                 // [2,2048,1024]

    __half *xf, *wh, *wl, *woh, *wol, *af;
    cudaGetSymbolAddress((void**)&xf, g_xf);
    cudaGetSymbolAddress((void**)&wh, g_wh);
    cudaGetSymbolAddress((void**)&wl, g_wl);
    cudaGetSymbolAddress((void**)&woh, g_woh);
    cudaGetSymbolAddress((void**)&wol, g_wol);
    cudaGetSymbolAddress((void**)&af, g_af);

    cudaFuncSetAttribute(gemm_f16<0>, cudaFuncAttributeMaxDynamicSharedMemorySize, GSMEM);
    cudaFuncSetAttribute(gemm_f16<1>, cudaFuncAttributeMaxDynamicSharedMemorySize, GSMEM);
    cudaFuncSetAttribute(attn_mma, cudaFuncAttributeMaxDynamicSharedMemorySize, ASMEM);

    // Prepass conversions
    convert_f16<<<512, 256>>>((const float4*)x, (uint2*)xf, 4096 * 1024 / 4);
    convert_split_f16s<<<512, 256>>>((const float4*)wqkv, (uint2*)wh, (uint2*)wl, 3072 * 1024 / 4);
    convert_split_f16s<<<256, 256>>>((const float4*)wo, (uint2*)woh, (uint2*)wol, 1024 * 1024 / 4);

    // QKV = x @ wqkv^T with scatter epilogue -> g_qh/ql/kh/kl/vh/vl
    gemm_f16<1><<<dim3(3072 / 128, 4096 / 128), 256, GSMEM>>>(xf, wh, wl, nullptr, 3072);

    // Attention -> g_af (fp16)
    attn_mma<<<dim3(SS / 128, HH, BB), 256, ASMEM>>>();

    // out = attn @ wo^T
    gemm_f16<0><<<dim3(1024 / 128, 4096 / 128), 256, GSMEM>>>(af, woh, wol, out, 1024);
}

// round 10
// speedup vs baseline: 1.4027x; 1.2780x over previous
#include <cuda_runtime.h>
#include <cuda_bf16.h>
#include <cuda_fp16.h>
#include <math.h>
#include <math_constants.h>
#include <cstdint>

// Problem constants
#define BB 2
#define SS 2048
#define DD 1024
#define HH 16
#define DHH 64

// log2(e)/8  (folded into Q so softmax is pure 2^x)
#define QSCALE 0.18033688011112042f

// ---------------- device scratch (no cudaMalloc allowed) ----------------
__device__ __align__(16) __half g_xf[4096 * 1024];          // x, fp16
__device__ __align__(16) __half g_wf[3072 * 1024];          // wqkv, fp16
__device__ __align__(16) __half g_wof[1024 * 1024];         // wo, fp16
__device__ __align__(16) __half g_af[4096 * 1024];          // attn out, fp16

// Q,K (bf16 hi/lo) and V (fp16 hi/lo) in [b][h][s][d] layout
__device__ __align__(16) __nv_bfloat16 g_qh[BB * HH * SS * DHH];
__device__ __align__(16) __nv_bfloat16 g_ql[BB * HH * SS * DHH];
__device__ __align__(16) __nv_bfloat16 g_kh[BB * HH * SS * DHH];
__device__ __align__(16) __nv_bfloat16 g_kl[BB * HH * SS * DHH];
__device__ __align__(16) __half       g_vh[BB * HH * SS * DHH];
__device__ __align__(16) __half       g_vl[BB * HH * SS * DHH];

// ============================ helpers ============================
__device__ __forceinline__ uint32_t smem_u32(const void* p) {
    uint32_t a;
    asm("{ .reg .u64 t; cvta.to.shared.u64 t, %1; cvt.u32.u64 %0, t; }" : "=r"(a) : "l"(p));
    return a;
}

__device__ __forceinline__ void ldm_x4(uint32_t* r, uint32_t addr) {
    asm volatile("ldmatrix.sync.aligned.m8n8.x4.shared.b16 {%0,%1,%2,%3}, [%4];"
                 : "=r"(r[0]), "=r"(r[1]), "=r"(r[2]), "=r"(r[3]) : "r"(addr));
}
__device__ __forceinline__ void ldm_x4_t(uint32_t* r, uint32_t addr) {
    asm volatile("ldmatrix.sync.aligned.m8n8.x4.trans.shared.b16 {%0,%1,%2,%3}, [%4];"
                 : "=r"(r[0]), "=r"(r[1]), "=r"(r[2]), "=r"(r[3]) : "r"(addr));
}

__device__ __forceinline__ void mma_bf16(float* d, const uint32_t* a, const uint32_t* b) {
    asm volatile(
        "mma.sync.aligned.m16n8k16.row.col.f32.bf16.bf16.f32 "
        "{%0,%1,%2,%3}, {%4,%5,%6,%7}, {%8,%9}, {%0,%1,%2,%3};"
        : "+f"(d[0]), "+f"(d[1]), "+f"(d[2]), "+f"(d[3])
        : "r"(a[0]), "r"(a[1]), "r"(a[2]), "r"(a[3]), "r"(b[0]), "r"(b[1]));
}
__device__ __forceinline__ void mma_f16(float* d, const uint32_t* a, const uint32_t* b) {
    asm volatile(
        "mma.sync.aligned.m16n8k16.row.col.f32.f16.f16.f32 "
        "{%0,%1,%2,%3}, {%4,%5,%6,%7}, {%8,%9}, {%0,%1,%2,%3};"
        : "+f"(d[0]), "+f"(d[1]), "+f"(d[2]), "+f"(d[3])
        : "r"(a[0]), "r"(a[1]), "r"(a[2]), "r"(a[3]), "r"(b[0]), "r"(b[1]));
}

__device__ __forceinline__ void cp16(uint32_t dst, const void* src) {
    asm volatile("cp.async.cg.shared.global [%0], [%1], 16;" :: "r"(dst), "l"(src));
}
#define CP_COMMIT() asm volatile("cp.async.commit_group;" ::: "memory")
#define CP_WAIT(n)  asm volatile("cp.async.wait_group %0;" :: "n"(n) : "memory")

__device__ __forceinline__ float ex2f(float x) {
    float y;
    asm("ex2.approx.ftz.f32 %0, %1;" : "=f"(y) : "f"(x));
    return y;
}
__device__ __forceinline__ uint32_t packh2(float a, float b) {
    __half2 h = __floats2half2_rn(a, b);
    return *(uint32_t*)&h;
}

__device__ __forceinline__ void store_split_bf16(__nv_bfloat16* H, __nv_bfloat16* L,
                                                 size_t idx, float v0, float v1) {
    __nv_bfloat16 h0 = __float2bfloat16(v0), h1 = __float2bfloat16(v1);
    __nv_bfloat16 l0 = __float2bfloat16(v0 - __bfloat162float(h0));
    __nv_bfloat16 l1 = __float2bfloat16(v1 - __bfloat162float(h1));
    *(__nv_bfloat162*)(H + idx) = __halves2bfloat162(h0, h1);
    *(__nv_bfloat162*)(L + idx) = __halves2bfloat162(l0, l1);
}
__device__ __forceinline__ void store_split_f16(__half* H, __half* L,
                                                size_t idx, float v0, float v1) {
    __half h0 = __float2half(v0), h1 = __float2half(v1);
    __half l0 = __float2half(v0 - __half2float(h0));
    __half l1 = __float2half(v1 - __half2float(h1));
    *(__half2*)(H + idx) = __halves2half2(h0, h1);
    *(__half2*)(L + idx) = __halves2half2(l0, l1);
}

// Prepass: fp32 -> fp16 (single)
__global__ __launch_bounds__(256) void convert_f16(const float4* __restrict__ src,
                                                   uint2* __restrict__ dst, int n4)
{
    for (int i = blockIdx.x * blockDim.x + threadIdx.x; i < n4; i += gridDim.x * blockDim.x) {
        float4 v = src[i];
        uint2 o;
        o.x = packh2(v.x, v.y);
        o.y = packh2(v.z, v.w);
        dst[i] = o;
    }
}

// Tile offset: two 64B k-rows packed per 128B SMEM line, SW128 swizzle (GEMM tiles).
__device__ __forceinline__ uint32_t toff(int r, int c) {
    uint32_t o = ((uint32_t)(r >> 1) << 7) | ((uint32_t)(r & 1) << 6) | ((uint32_t)c << 4);
    return o ^ ((o >> 3) & 0x70);
}
// 128B-row SW128 swizzle (attention tiles)
__device__ __forceinline__ uint32_t soff(int r, int c) {
    uint32_t o = (uint32_t)r * 128 + (uint32_t)c * 16;
    return o ^ ((o >> 3) & 0x70);
}

// ---------------------------------------------------------------------------
// Plain fp16 GEMM NT: C[m,n] = sum_k A[m,k]*B[n,k], K=1024.
// 128x128 CTA tile, BK=32, 8 warps (2m x 4n), warp tile 64x32.
// 4-stage cp.async pipeline, one __syncthreads per chunk, 2 CTAs/SM.
// Buffer: A 8K | B 8K = 16KB, x4 stages = 64KB.
// MODE 0: C = fp32 out (proj).  MODE 1: QKV scatter epilogue.
// ---------------------------------------------------------------------------
#define GSMEM (4 * 16384)

template <int MODE>
__global__ __launch_bounds__(256, 2) void gemm_f16(const __half* __restrict__ A,
                                                   const __half* __restrict__ B,
                                                   float* __restrict__ C, int N)
{
    extern __shared__ __align__(1024) uint8_t smem[];
    const uint32_t sb = smem_u32(smem);

    const int tid = threadIdx.x;
    const int lane = tid & 31;
    const int wid = tid >> 5;
    const int wm = wid & 1;
    const int wn = wid >> 1;
    const int bm = blockIdx.y * 128;
    const int bn = blockIdx.x * 128;

    // each thread loads one contiguous 32B segment: row m0, chunks c0 and c0+1
    const int m0 = tid >> 1;
    const int c0 = (tid & 1) * 2;
    const uint32_t so0 = toff(m0, c0);
    const uint32_t so1 = toff(m0, c0 + 1);

    const __half* pA = A + (size_t)(bm + m0) * 1024 + c0 * 8;
    const __half* pB = B + (size_t)(bn + m0) * 1024 + c0 * 8;

    const int a_row = wm * 64 + (lane & 15);
    const int a_k16 = lane >> 4;
    const int b_row = wn * 32 + (lane & 7) + ((lane >> 4) & 1) * 8;
    const int b_k16 = (lane >> 3) & 1;

    float acc[4][4][4] = {};

    // prologue: stage chunks 0..2
#pragma unroll
    for (int p = 0; p < 3; p++) {
        const uint32_t s = sb + p * 16384;
        const int ko = p * 32;
        cp16(s + so0, pA + ko);          cp16(s + so1, pA + ko + 8);
        cp16(s + 8192 + so0, pB + ko);   cp16(s + 8192 + so1, pB + ko + 8);
        CP_COMMIT();
    }

    int slot = 0, nslot = 3;
    for (int kc = 0; kc < 32; kc++) {
        if (kc < 30) CP_WAIT(2);
        else if (kc == 30) CP_WAIT(1);
        else CP_WAIT(0);
        __syncthreads();

        // issue loads for chunk kc+3 into nslot
        if (kc + 3 < 32) {
            const uint32_t s = sb + nslot * 16384;
            const int ko = (kc + 3) * 32;
            cp16(s + so0, pA + ko);          cp16(s + so1, pA + ko + 8);
            cp16(s + 8192 + so0, pB + ko);   cp16(s + 8192 + so1, pB + ko + 8);
            CP_COMMIT();
        }

        const uint32_t buf = sb + slot * 16384;
#pragma unroll
        for (int ks = 0; ks < 2; ks++) {
            uint32_t a[4][4], bfr[4][2];
#pragma unroll
            for (int mt = 0; mt < 4; mt++) {
                const uint32_t off = toff(a_row + mt * 16, ks * 2 + a_k16);
                ldm_x4(a[mt], buf + off);
            }
#pragma unroll
            for (int nt2 = 0; nt2 < 2; nt2++) {
                const uint32_t off = toff(b_row + nt2 * 16, ks * 2 + b_k16);
                uint32_t rh[4];
                ldm_x4(rh, buf + 8192 + off);
                bfr[nt2 * 2][0] = rh[0]; bfr[nt2 * 2][1] = rh[1];
                bfr[nt2 * 2 + 1][0] = rh[2]; bfr[nt2 * 2 + 1][1] = rh[3];
            }
#pragma unroll
            for (int mt = 0; mt < 4; mt++)
#pragma unroll
                for (int nt = 0; nt < 4; nt++)
                    mma_f16(acc[mt][nt], a[mt], bfr[nt]);
        }
        slot = (slot == 3) ? 0 : slot + 1;
        nslot = (nslot == 3) ? 0 : nslot + 1;
    }

    if (MODE == 0) {
#pragma unroll
        for (int mt = 0; mt < 4; mt++) {
            const int r0 = bm + wm * 64 + mt * 16 + (lane >> 2);
#pragma unroll
            for (int nt = 0; nt < 4; nt++) {
                const int c = bn + wn * 32 + nt * 8 + (lane & 3) * 2;
                float2 v0 = {acc[mt][nt][0], acc[mt][nt][1]};
                float2 v1 = {acc[mt][nt][2], acc[mt][nt][3]};
                *(float2*)(C + (size_t)r0 * N + c) = v0;
                *(float2*)(C + (size_t)(r0 + 8) * N + c) = v1;
            }
        }
    } else {
        // QKV scatter: row=token, col in [0,3072)
#pragma unroll
        for (int mt = 0; mt < 4; mt++) {
            const int row = bm + wm * 64 + mt * 16 + (lane >> 2);
#pragma unroll
            for (int nt = 0; nt < 4; nt++) {
                const int c = bn + wn * 32 + nt * 8 + (lane & 3) * 2;
                const int which = c >> 10;
                const int hh = (c >> 6) & 15;
                const int d = c & 63;
#pragma unroll
                for (int half = 0; half < 2; half++) {
                    const int r = row + half * 8;
                    const int bb = r >> 11;
                    const int s = r & 2047;
                    const size_t idx = (((size_t)(bb * 16 + hh)) * SS + s) * 64 + d;
                    float v0 = acc[mt][nt][half * 2];
                    float v1 = acc[mt][nt][half * 2 + 1];
                    if (which == 0) {
                        store_split_bf16(g_qh, g_ql, idx, v0 * QSCALE, v1 * QSCALE);
                    } else if (which == 1) {
                        store_split_bf16(g_kh, g_kl, idx, v0, v1);
                    } else {
                        store_split_f16(g_vh, g_vl, idx, v0, v1);
                    }
                }
            }
        }
    }
}

// ---------------------------------------------------------------------------
// Flash attention on mma.sync (validated in R5-R8).
// SMEM: Qh 16K | Ql 16K | K bufs 2x(8K+8K) | V bufs 2x(8K+8K) = 96KB.
// ---------------------------------------------------------------------------
#define ASMEM 98304

__device__ __forceinline__ void attn_load_kv(uint32_t sb, size_t bh, int kt, int buf, int tid)
{
#pragma unroll
    for (int i = 0; i < 8; i++) {
        const int id = tid + 256 * i;
        const int t = id >> 9;        // 0 Kh,1 Kl,2 Vh,3 Vl
        const int w = id & 511;
        const int r = w >> 3, c = w & 7;
        const uint32_t swz = soff(r, c);
        const size_t gidx = (bh * SS + (size_t)kt * 64 + r) * 64 + c * 8;
        uint32_t dst;
        const void* src;
        if (t == 0)      { dst = sb + 32768 + buf * 16384 + swz;        src = g_kh + gidx; }
        else if (t == 1) { dst = sb + 32768 + buf * 16384 + 8192 + swz; src = g_kl + gidx; }
        else if (t == 2) { dst = sb + 65536 + buf * 16384 + swz;        src = g_vh + gidx; }
        else             { dst = sb + 65536 + buf * 16384 + 8192 + swz; src = g_vl + gidx; }
        cp16(dst, src);
    }
}

__global__ __launch_bounds__(256) void attn_mma()
{
    extern __shared__ __align__(1024) uint8_t sm[];
    const uint32_t sb = smem_u32(sm);
    const int qt = (int)gridDim.x - 1 - (int)blockIdx.x;  // heavy tiles first
    const int h = blockIdx.y;
    const int b = blockIdx.z;
    const int tid = threadIdx.x;
    const int lane = tid & 31;
    const int wid = tid >> 5;
    const size_t bh = (size_t)(b * HH + h);
    const int nkt = 2 * qt + 2;

#pragma unroll
    for (int i = 0; i < 8; i++) {
        const int id = tid + 256 * i;
        const int t = id >> 10;       // 0 Qh, 1 Ql
        const int w = id & 1023;
        const int r = w >> 3, c = w & 7;
        const uint32_t dst = sb + t * 16384 + soff(r, c);
        const size_t gidx = (bh * SS + (size_t)qt * 128 + r) * 64 + c * 8;
        cp16(dst, t == 0 ? (const void*)(g_qh + gidx) : (const void*)(g_ql + gidx));
    }
    attn_load_kv(sb, bh, 0, 0, tid);
    CP_COMMIT();
    attn_load_kv(sb, bh, 1, 1, tid);
    CP_COMMIT();

    float m1 = -CUDART_INF_F, m2 = -CUDART_INF_F;
    float o[8][4] = {};
    float lac[4] = {};
    const uint32_t ones2[2] = {0x3C003C00u, 0x3C003C00u};

    const int rg1 = qt * 128 + wid * 16 + (lane >> 2);

    for (int kt = 0; kt < nkt; kt++) {
        CP_WAIT(1);
        __syncthreads();

        const uint32_t kb = sb + 32768 + (kt & 1) * 16384;
        const uint32_t vb = sb + 65536 + (kt & 1) * 16384;

        const bool skipall = (kt == 2 * qt + 1) && (wid < 4);
        if (!skipall) {
            float s[8][4];
#pragma unroll
            for (int nt = 0; nt < 8; nt++)
#pragma unroll
                for (int j = 0; j < 4; j++) s[nt][j] = 0.f;

#pragma unroll
            for (int ks = 0; ks < 4; ks++) {
                uint32_t qa[4], ql[4];
                const uint32_t offA = soff(wid * 16 + (lane & 15), ks * 2 + (lane >> 4));
                ldm_x4(qa, sb + offA);
                ldm_x4(ql, sb + 16384 + offA);
#pragma unroll
                for (int nb = 0; nb < 4; nb++) {
                    const uint32_t offB = soff(nb * 16 + (lane & 7) + ((lane >> 4) & 1) * 8,
                                               ks * 2 + ((lane >> 3) & 1));
                    uint32_t rh[4], rl[4];
                    ldm_x4(rh, kb + offB);
                    ldm_x4(rl, kb + 8192 + offB);
                    mma_bf16(s[nb * 2], qa, rh);
                    mma_bf16(s[nb * 2], qa, rl);
                    mma_bf16(s[nb * 2], ql, rh);
                    mma_bf16(s[nb * 2 + 1], qa, rh + 2);
                    mma_bf16(s[nb * 2 + 1], qa, rl + 2);
                    mma_bf16(s[nb * 2 + 1], ql, rh + 2);
                }
            }

            const bool domask = (kt == 2 * qt && wid < 4) || (kt == 2 * qt + 1 && wid >= 4);
            if (domask) {
#pragma unroll
                for (int nt = 0; nt < 8; nt++) {
                    const int cg = kt * 64 + nt * 8 + (lane & 3) * 2;
#pragma unroll
                    for (int j = 0; j < 4; j++) {
                        const int col = cg + (j & 1);
                        const int row = rg1 + ((j >> 1) << 3);
                        if (col > row) s[nt][j] = -1e30f;
                    }
                }
            }

            float t1 = -CUDART_INF_F, t2 = -CUDART_INF_F;
#pragma unroll
            for (int nt = 0; nt < 8; nt++) {
                t1 = fmaxf(t1, fmaxf(s[nt][0], s[nt][1]));
                t2 = fmaxf(t2, fmaxf(s[nt][2], s[nt][3]));
            }
            t1 = fmaxf(t1, __shfl_xor_sync(0xffffffffu, t1, 1));
            t1 = fmaxf(t1, __shfl_xor_sync(0xffffffffu, t1, 2));
            t2 = fmaxf(t2, __shfl_xor_sync(0xffffffffu, t2, 1));
            t2 = fmaxf(t2, __shfl_xor_sync(0xffffffffu, t2, 2));
            const float mn1 = fmaxf(m1, t1);
            const float mn2 = fmaxf(m2, t2);
            const float cr1 = ex2f(m1 - mn1);
            const float cr2 = ex2f(m2 - mn2);
            m1 = mn1; m2 = mn2;

            uint32_t p1[8], p2[8];
#pragma unroll
            for (int nt = 0; nt < 8; nt++) {
                p1[nt] = packh2(ex2f(s[nt][0] - mn1), ex2f(s[nt][1] - mn1));
                p2[nt] = packh2(ex2f(s[nt][2] - mn2), ex2f(s[nt][3] - mn2));
            }
#pragma unroll
            for (int nt = 0; nt < 8; nt++) {
                o[nt][0] *= cr1; o[nt][1] *= cr1;
                o[nt][2] *= cr2; o[nt][3] *= cr2;
            }
            lac[0] *= cr1; lac[1] *= cr1; lac[2] *= cr2; lac[3] *= cr2;

#pragma unroll
            for (int ks = 0; ks < 4; ks++) {
                uint32_t A[4] = {p1[ks * 2], p2[ks * 2], p1[ks * 2 + 1], p2[ks * 2 + 1]};
#pragma unroll
                for (int nb = 0; nb < 4; nb++) {
                    const uint32_t offV = soff(ks * 16 + (lane & 15), nb * 2 + (lane >> 4));
                    uint32_t vh[4], vl[4];
                    ldm_x4_t(vh, vb + offV);
                    ldm_x4_t(vl, vb + 8192 + offV);
                    mma_f16(o[nb * 2], A, vh);
                    mma_f16(o[nb * 2], A, vl);
                    mma_f16(o[nb * 2 + 1], A, vh + 2);
                    mma_f16(o[nb * 2 + 1], A, vl + 2);
                }
                mma_f16(lac, A, ones2);
            }
        }

        __syncthreads();
        if (kt + 2 < nkt) attn_load_kv(sb, bh, kt + 2, kt & 1, tid);
        CP_COMMIT();
    }

    // epilogue: normalize, write single fp16 [token][1024]
    const float inv1 = 1.f / lac[0];
    const float inv2 = 1.f / lac[2];
    const size_t tok1 = (size_t)(b * SS + qt * 128 + wid * 16 + (lane >> 2));
#pragma unroll
    for (int nt = 0; nt < 8; nt++) {
        const int col = h * 64 + nt * 8 + (lane & 3) * 2;
        const uint32_t u1 = packh2(o[nt][0] * inv1, o[nt][1] * inv1);
        const uint32_t u2 = packh2(o[nt][2] * inv2, o[nt][3] * inv2);
        *(uint32_t*)(g_af + tok1 * 1024 + col) = u1;
        *(uint32_t*)(g_af + (tok1 + 8) * 1024 + col) = u2;
    }
}

// ---------------------------------------------------------------------------
extern "C" void kernel_launch(void* const* d_in, const int* in_sizes, int n_in,
                              void* d_out, int out_size)
{
    const float* x    = (const float*)d_in[0];  // [2,2048,1024]
    const float* wqkv = (const float*)d_in[1];  // [3072,1024]
    const float* wo   = (const float*)d_in[2];  // [1024,1024]
    float* out = (float*)d_out;                 // [2,2048,1024]

    __half *xf, *wf, *wof, *af;
    cudaGetSymbolAddress((void**)&xf, g_xf);
    cudaGetSymbolAddress((void**)&wf, g_wf);
    cudaGetSymbolAddress((void**)&wof, g_wof);
    cudaGetSymbolAddress((void**)&af, g_af);

    cudaFuncSetAttribute(gemm_f16<0>, cudaFuncAttributeMaxDynamicSharedMemorySize, GSMEM);
    cudaFuncSetAttribute(gemm_f16<1>, cudaFuncAttributeMaxDynamicSharedMemorySize, GSMEM);
    cudaFuncSetAttribute(attn_mma, cudaFuncAttributeMaxDynamicSharedMemorySize, ASMEM);

    // Prepass conversions (all single fp16)
    convert_f16<<<512, 256>>>((const float4*)x, (uint2*)xf, 4096 * 1024 / 4);
    convert_f16<<<512, 256>>>((const float4*)wqkv, (uint2*)wf, 3072 * 1024 / 4);
    convert_f16<<<256, 256>>>((const float4*)wo, (uint2*)wof, 1024 * 1024 / 4);

    // QKV = x @ wqkv^T with scatter epilogue -> g_qh/ql/kh/kl/vh/vl
    gemm_f16<1><<<dim3(3072 / 128, 4096 / 128), 256, GSMEM>>>(xf, wf, nullptr, 3072);

    // Attention -> g_af (fp16)
    attn_mma<<<dim3(SS / 128, HH, BB), 256, ASMEM>>>();

    // out = attn @ wo^T
    gemm_f16<0><<<dim3(1024 / 128, 4096 / 128), 256, GSMEM>>>(af, wof, out, 1024);
}

// round 11
// speedup vs baseline: 1.8833x; 1.3426x over previous
#include <cuda_runtime.h>
#include <cuda_bf16.h>
#include <cuda_fp16.h>
#include <math.h>
#include <math_constants.h>
#include <cstdint>

// Problem constants
#define BB 2
#define SS 2048
#define DD 1024
#define HH 16
#define DHH 64

// log2(e)/8  (folded into Q so softmax is pure 2^x)
#define QSCALE 0.18033688011112042f

// ---------------- device scratch (no cudaMalloc allowed) ----------------
__device__ __align__(16) __half g_xf[4096 * 1024];          // x, fp16
__device__ __align__(16) __half g_wf[3072 * 1024];          // wqkv, fp16
__device__ __align__(16) __half g_wof[1024 * 1024];         // wo, fp16
__device__ __align__(16) __half g_af[4096 * 1024];          // attn out, fp16

// Q (pre-scaled), K, V fp16 in [b][h][s][d] layout
__device__ __align__(16) __half g_qf[BB * HH * SS * DHH];
__device__ __align__(16) __half g_kf[BB * HH * SS * DHH];
__device__ __align__(16) __half g_vf[BB * HH * SS * DHH];

// ============================ helpers ============================
__device__ __forceinline__ uint32_t smem_u32(const void* p) {
    uint32_t a;
    asm("{ .reg .u64 t; cvta.to.shared.u64 t, %1; cvt.u32.u64 %0, t; }" : "=r"(a) : "l"(p));
    return a;
}

__device__ __forceinline__ void ldm_x4(uint32_t* r, uint32_t addr) {
    asm volatile("ldmatrix.sync.aligned.m8n8.x4.shared.b16 {%0,%1,%2,%3}, [%4];"
                 : "=r"(r[0]), "=r"(r[1]), "=r"(r[2]), "=r"(r[3]) : "r"(addr));
}
__device__ __forceinline__ void ldm_x4_t(uint32_t* r, uint32_t addr) {
    asm volatile("ldmatrix.sync.aligned.m8n8.x4.trans.shared.b16 {%0,%1,%2,%3}, [%4];"
                 : "=r"(r[0]), "=r"(r[1]), "=r"(r[2]), "=r"(r[3]) : "r"(addr));
}

__device__ __forceinline__ void mma_f16(float* d, const uint32_t* a, const uint32_t* b) {
    asm volatile(
        "mma.sync.aligned.m16n8k16.row.col.f32.f16.f16.f32 "
        "{%0,%1,%2,%3}, {%4,%5,%6,%7}, {%8,%9}, {%0,%1,%2,%3};"
        : "+f"(d[0]), "+f"(d[1]), "+f"(d[2]), "+f"(d[3])
        : "r"(a[0]), "r"(a[1]), "r"(a[2]), "r"(a[3]), "r"(b[0]), "r"(b[1]));
}

__device__ __forceinline__ void cp16(uint32_t dst, const void* src) {
    asm volatile("cp.async.cg.shared.global [%0], [%1], 16;" :: "r"(dst), "l"(src));
}
#define CP_COMMIT() asm volatile("cp.async.commit_group;" ::: "memory")
#define CP_WAIT(n)  asm volatile("cp.async.wait_group %0;" :: "n"(n) : "memory")

__device__ __forceinline__ float ex2f(float x) {
    float y;
    asm("ex2.approx.ftz.f32 %0, %1;" : "=f"(y) : "f"(x));
    return y;
}
__device__ __forceinline__ uint32_t packh2(float a, float b) {
    __half2 h = __floats2half2_rn(a, b);
    return *(uint32_t*)&h;
}

// Prepass: fp32 -> fp16 (single)
__global__ __launch_bounds__(256) void convert_f16(const float4* __restrict__ src,
                                                   uint2* __restrict__ dst, int n4)
{
    for (int i = blockIdx.x * blockDim.x + threadIdx.x; i < n4; i += gridDim.x * blockDim.x) {
        float4 v = src[i];
        uint2 o;
        o.x = packh2(v.x, v.y);
        o.y = packh2(v.z, v.w);
        dst[i] = o;
    }
}

// Tile offset: two 64B k-rows packed per 128B SMEM line, SW128 swizzle (GEMM tiles).
__device__ __forceinline__ uint32_t toff(int r, int c) {
    uint32_t o = ((uint32_t)(r >> 1) << 7) | ((uint32_t)(r & 1) << 6) | ((uint32_t)c << 4);
    return o ^ ((o >> 3) & 0x70);
}
// 128B-row SW128 swizzle (attention tiles)
__device__ __forceinline__ uint32_t soff(int r, int c) {
    uint32_t o = (uint32_t)r * 128 + (uint32_t)c * 16;
    return o ^ ((o >> 3) & 0x70);
}

// ---------------------------------------------------------------------------
// Plain fp16 GEMM NT: C[m,n] = sum_k A[m,k]*B[n,k], K=1024.
// 128x128 CTA tile, BK=32, 8 warps (2m x 4n), warp tile 64x32.
// 4-stage cp.async pipeline, one __syncthreads per chunk, 2 CTAs/SM.
// MODE 0: C = fp32 out (proj).  MODE 1: QKV scatter epilogue (fp16 q/k/v).
// ---------------------------------------------------------------------------
#define GSMEM (4 * 16384)

template <int MODE>
__global__ __launch_bounds__(256, 2) void gemm_f16(const __half* __restrict__ A,
                                                   const __half* __restrict__ B,
                                                   float* __restrict__ C, int N)
{
    extern __shared__ __align__(1024) uint8_t smem[];
    const uint32_t sb = smem_u32(smem);

    const int tid = threadIdx.x;
    const int lane = tid & 31;
    const int wid = tid >> 5;
    const int wm = wid & 1;
    const int wn = wid >> 1;
    const int bm = blockIdx.y * 128;
    const int bn = blockIdx.x * 128;

    const int m0 = tid >> 1;
    const int c0 = (tid & 1) * 2;
    const uint32_t so0 = toff(m0, c0);
    const uint32_t so1 = toff(m0, c0 + 1);

    const __half* pA = A + (size_t)(bm + m0) * 1024 + c0 * 8;
    const __half* pB = B + (size_t)(bn + m0) * 1024 + c0 * 8;

    const int a_row = wm * 64 + (lane & 15);
    const int a_k16 = lane >> 4;
    const int b_row = wn * 32 + (lane & 7) + ((lane >> 4) & 1) * 8;
    const int b_k16 = (lane >> 3) & 1;

    float acc[4][4][4] = {};

#pragma unroll
    for (int p = 0; p < 3; p++) {
        const uint32_t s = sb + p * 16384;
        const int ko = p * 32;
        cp16(s + so0, pA + ko);          cp16(s + so1, pA + ko + 8);
        cp16(s + 8192 + so0, pB + ko);   cp16(s + 8192 + so1, pB + ko + 8);
        CP_COMMIT();
    }

    int slot = 0, nslot = 3;
    for (int kc = 0; kc < 32; kc++) {
        if (kc < 30) CP_WAIT(2);
        else if (kc == 30) CP_WAIT(1);
        else CP_WAIT(0);
        __syncthreads();

        if (kc + 3 < 32) {
            const uint32_t s = sb + nslot * 16384;
            const int ko = (kc + 3) * 32;
            cp16(s + so0, pA + ko);          cp16(s + so1, pA + ko + 8);
            cp16(s + 8192 + so0, pB + ko);   cp16(s + 8192 + so1, pB + ko + 8);
            CP_COMMIT();
        }

        const uint32_t buf = sb + slot * 16384;
#pragma unroll
        for (int ks = 0; ks < 2; ks++) {
            uint32_t a[4][4], bfr[4][2];
#pragma unroll
            for (int mt = 0; mt < 4; mt++) {
                const uint32_t off = toff(a_row + mt * 16, ks * 2 + a_k16);
                ldm_x4(a[mt], buf + off);
            }
#pragma unroll
            for (int nt2 = 0; nt2 < 2; nt2++) {
                const uint32_t off = toff(b_row + nt2 * 16, ks * 2 + b_k16);
                uint32_t rh[4];
                ldm_x4(rh, buf + 8192 + off);
                bfr[nt2 * 2][0] = rh[0]; bfr[nt2 * 2][1] = rh[1];
                bfr[nt2 * 2 + 1][0] = rh[2]; bfr[nt2 * 2 + 1][1] = rh[3];
            }
#pragma unroll
            for (int mt = 0; mt < 4; mt++)
#pragma unroll
                for (int nt = 0; nt < 4; nt++)
                    mma_f16(acc[mt][nt], a[mt], bfr[nt]);
        }
        slot = (slot == 3) ? 0 : slot + 1;
        nslot = (nslot == 3) ? 0 : nslot + 1;
    }

    if (MODE == 0) {
#pragma unroll
        for (int mt = 0; mt < 4; mt++) {
            const int r0 = bm + wm * 64 + mt * 16 + (lane >> 2);
#pragma unroll
            for (int nt = 0; nt < 4; nt++) {
                const int c = bn + wn * 32 + nt * 8 + (lane & 3) * 2;
                float2 v0 = {acc[mt][nt][0], acc[mt][nt][1]};
                float2 v1 = {acc[mt][nt][2], acc[mt][nt][3]};
                *(float2*)(C + (size_t)r0 * N + c) = v0;
                *(float2*)(C + (size_t)(r0 + 8) * N + c) = v1;
            }
        }
    } else {
        // QKV scatter: fp16 single, Q pre-scaled
#pragma unroll
        for (int mt = 0; mt < 4; mt++) {
            const int row = bm + wm * 64 + mt * 16 + (lane >> 2);
#pragma unroll
            for (int nt = 0; nt < 4; nt++) {
                const int c = bn + wn * 32 + nt * 8 + (lane & 3) * 2;
                const int which = c >> 10;
                const int hh = (c >> 6) & 15;
                const int d = c & 63;
#pragma unroll
                for (int half = 0; half < 2; half++) {
                    const int r = row + half * 8;
                    const int bb = r >> 11;
                    const int s = r & 2047;
                    const size_t idx = (((size_t)(bb * 16 + hh)) * SS + s) * 64 + d;
                    float v0 = acc[mt][nt][half * 2];
                    float v1 = acc[mt][nt][half * 2 + 1];
                    if (which == 0) {
                        *(uint32_t*)(g_qf + idx) = packh2(v0 * QSCALE, v1 * QSCALE);
                    } else if (which == 1) {
                        *(uint32_t*)(g_kf + idx) = packh2(v0, v1);
                    } else {
                        *(uint32_t*)(g_vf + idx) = packh2(v0, v1);
                    }
                }
            }
        }
    }
}

// ---------------------------------------------------------------------------
// Flash attention, all fp16 operands.
// CTA = (qt, h, b), 256 thr, 8 warps x 16 q-rows. S/P in registers.
// SMEM: Q 16K | K bufs 2x8K | V bufs 2x8K = 48KB -> 2 CTAs/SM.
// ---------------------------------------------------------------------------
#define ASMEM 49152

__device__ __forceinline__ void attn_load_kv(uint32_t sb, size_t bh, int kt, int buf, int tid)
{
#pragma unroll
    for (int i = 0; i < 4; i++) {
        const int id = tid + 256 * i;
        const int t = id >> 9;        // 0 K, 1 V
        const int w = id & 511;
        const int r = w >> 3, c = w & 7;
        const uint32_t swz = soff(r, c);
        const size_t gidx = (bh * SS + (size_t)kt * 64 + r) * 64 + c * 8;
        if (t == 0) cp16(sb + 16384 + buf * 8192 + swz, g_kf + gidx);
        else        cp16(sb + 32768 + buf * 8192 + swz, g_vf + gidx);
    }
}

__global__ __launch_bounds__(256, 2) void attn_mma()
{
    extern __shared__ __align__(1024) uint8_t sm[];
    const uint32_t sb = smem_u32(sm);
    const int qt = (int)gridDim.x - 1 - (int)blockIdx.x;  // heavy tiles first
    const int h = blockIdx.y;
    const int b = blockIdx.z;
    const int tid = threadIdx.x;
    const int lane = tid & 31;
    const int wid = tid >> 5;
    const size_t bh = (size_t)(b * HH + h);
    const int nkt = 2 * qt + 2;

    // prologue: Q tile (16KB) + KV(0), then KV(1)
#pragma unroll
    for (int i = 0; i < 4; i++) {
        const int id = tid + 256 * i;
        const int r = id >> 3, c = id & 7;
        const size_t gidx = (bh * SS + (size_t)qt * 128 + r) * 64 + c * 8;
        cp16(sb + soff(r, c), g_qf + gidx);
    }
    attn_load_kv(sb, bh, 0, 0, tid);
    CP_COMMIT();
    attn_load_kv(sb, bh, 1, 1, tid);
    CP_COMMIT();

    float m1 = -CUDART_INF_F, m2 = -CUDART_INF_F;
    float o[8][4] = {};
    float lac[4] = {};
    const uint32_t ones2[2] = {0x3C003C00u, 0x3C003C00u};

    const int rg1 = qt * 128 + wid * 16 + (lane >> 2);

    for (int kt = 0; kt < nkt; kt++) {
        CP_WAIT(1);
        __syncthreads();

        const uint32_t kb = sb + 16384 + (kt & 1) * 8192;
        const uint32_t vb = sb + 32768 + (kt & 1) * 8192;

        const bool skipall = (kt == 2 * qt + 1) && (wid < 4);
        if (!skipall) {
            // ---- S = Q @ K^T (fp16) ----
            float s[8][4];
#pragma unroll
            for (int nt = 0; nt < 8; nt++)
#pragma unroll
                for (int j = 0; j < 4; j++) s[nt][j] = 0.f;

#pragma unroll
            for (int ks = 0; ks < 4; ks++) {
                uint32_t qa[4];
                const uint32_t offA = soff(wid * 16 + (lane & 15), ks * 2 + (lane >> 4));
                ldm_x4(qa, sb + offA);
#pragma unroll
                for (int nb = 0; nb < 4; nb++) {
                    const uint32_t offB = soff(nb * 16 + (lane & 7) + ((lane >> 4) & 1) * 8,
                                               ks * 2 + ((lane >> 3) & 1));
                    uint32_t rh[4];
                    ldm_x4(rh, kb + offB);
                    mma_f16(s[nb * 2], qa, rh);
                    mma_f16(s[nb * 2 + 1], qa, rh + 2);
                }
            }

            const bool domask = (kt == 2 * qt && wid < 4) || (kt == 2 * qt + 1 && wid >= 4);
            if (domask) {
#pragma unroll
                for (int nt = 0; nt < 8; nt++) {
                    const int cg = kt * 64 + nt * 8 + (lane & 3) * 2;
#pragma unroll
                    for (int j = 0; j < 4; j++) {
                        const int col = cg + (j & 1);
                        const int row = rg1 + ((j >> 1) << 3);
                        if (col > row) s[nt][j] = -1e30f;
                    }
                }
            }

            // ---- online softmax (log2 domain) ----
            float t1 = -CUDART_INF_F, t2 = -CUDART_INF_F;
#pragma unroll
            for (int nt = 0; nt < 8; nt++) {
                t1 = fmaxf(t1, fmaxf(s[nt][0], s[nt][1]));
                t2 = fmaxf(t2, fmaxf(s[nt][2], s[nt][3]));
            }
            t1 = fmaxf(t1, __shfl_xor_sync(0xffffffffu, t1, 1));
            t1 = fmaxf(t1, __shfl_xor_sync(0xffffffffu, t1, 2));
            t2 = fmaxf(t2, __shfl_xor_sync(0xffffffffu, t2, 1));
            t2 = fmaxf(t2, __shfl_xor_sync(0xffffffffu, t2, 2));
            const float mn1 = fmaxf(m1, t1);
            const float mn2 = fmaxf(m2, t2);
            const float cr1 = ex2f(m1 - mn1);
            const float cr2 = ex2f(m2 - mn2);
            m1 = mn1; m2 = mn2;

            uint32_t p1[8], p2[8];
#pragma unroll
            for (int nt = 0; nt < 8; nt++) {
                p1[nt] = packh2(ex2f(s[nt][0] - mn1), ex2f(s[nt][1] - mn1));
                p2[nt] = packh2(ex2f(s[nt][2] - mn2), ex2f(s[nt][3] - mn2));
            }
#pragma unroll
            for (int nt = 0; nt < 8; nt++) {
                o[nt][0] *= cr1; o[nt][1] *= cr1;
                o[nt][2] *= cr2; o[nt][3] *= cr2;
            }
            lac[0] *= cr1; lac[1] *= cr1; lac[2] *= cr2; lac[3] *= cr2;

            // ---- O += P @ V, l += P @ 1 ----
#pragma unroll
            for (int ks = 0; ks < 4; ks++) {
                uint32_t A[4] = {p1[ks * 2], p2[ks * 2], p1[ks * 2 + 1], p2[ks * 2 + 1]};
#pragma unroll
                for (int nb = 0; nb < 4; nb++) {
                    const uint32_t offV = soff(ks * 16 + (lane & 15), nb * 2 + (lane >> 4));
                    uint32_t vh[4];
                    ldm_x4_t(vh, vb + offV);
                    mma_f16(o[nb * 2], A, vh);
                    mma_f16(o[nb * 2 + 1], A, vh + 2);
                }
                mma_f16(lac, A, ones2);
            }
        }

        __syncthreads();
        if (kt + 2 < nkt) attn_load_kv(sb, bh, kt + 2, kt & 1, tid);
        CP_COMMIT();
    }

    // epilogue: normalize, write fp16 [token][1024]
    const float inv1 = 1.f / lac[0];
    const float inv2 = 1.f / lac[2];
    const size_t tok1 = (size_t)(b * SS + qt * 128 + wid * 16 + (lane >> 2));
#pragma unroll
    for (int nt = 0; nt < 8; nt++) {
        const int col = h * 64 + nt * 8 + (lane & 3) * 2;
        *(uint32_t*)(g_af + tok1 * 1024 + col) = packh2(o[nt][0] * inv1, o[nt][1] * inv1);
        *(uint32_t*)(g_af + (tok1 + 8) * 1024 + col) = packh2(o[nt][2] * inv2, o[nt][3] * inv2);
    }
}

// ---------------------------------------------------------------------------
extern "C" void kernel_launch(void* const* d_in, const int* in_sizes, int n_in,
                              void* d_out, int out_size)
{
    const float* x    = (const float*)d_in[0];  // [2,2048,1024]
    const float* wqkv = (const float*)d_in[1];  // [3072,1024]
    const float* wo   = (const float*)d_in[2];  // [1024,1024]
    float* out = (float*)d_out;                 // [2,2048,1024]

    __half *xf, *wf, *wof, *af;
    cudaGetSymbolAddress((void**)&xf, g_xf);
    cudaGetSymbolAddress((void**)&wf, g_wf);
    cudaGetSymbolAddress((void**)&wof, g_wof);
    cudaGetSymbolAddress((void**)&af, g_af);

    cudaFuncSetAttribute(gemm_f16<0>, cudaFuncAttributeMaxDynamicSharedMemorySize, GSMEM);
    cudaFuncSetAttribute(gemm_f16<1>, cudaFuncAttributeMaxDynamicSharedMemorySize, GSMEM);
    cudaFuncSetAttribute(attn_mma, cudaFuncAttributeMaxDynamicSharedMemorySize, ASMEM);

    // Prepass conversions
    convert_f16<<<512, 256>>>((const float4*)x, (uint2*)xf, 4096 * 1024 / 4);
    convert_f16<<<512, 256>>>((const float4*)wqkv, (uint2*)wf, 3072 * 1024 / 4);
    convert_f16<<<256, 256>>>((const float4*)wo, (uint2*)wof, 1024 * 1024 / 4);

    // QKV = x @ wqkv^T with scatter epilogue -> g_qf/g_kf/g_vf
    gemm_f16<1><<<dim3(3072 / 128, 4096 / 128), 256, GSMEM>>>(xf, wf, nullptr, 3072);

    // Attention -> g_af (fp16)
    attn_mma<<<dim3(SS / 128, HH, BB), 256, ASMEM>>>();

    // out = attn @ wo^T
    gemm_f16<0><<<dim3(1024 / 128, 4096 / 128), 256, GSMEM>>>(af, wof, out, 1024);
}